// round 9
// baseline (speedup 1.0000x reference)
#include <cuda_runtime.h>
#include <cstdint>

#define DNF  133
#define DPAD 136   // padded feature stride: 544 B rows, float4-aligned
#define MAXN 50000
#define MAXE 800000
#define NGRAPH 256

// ---------------- static device scratch (zero-initialized at load) ----------------
__device__ float g_hp[MAXN * DPAD];    // (X@W) * dinv[row]; cols 133..135 stay 0
__device__ float g_feat[MAXN * DPAD];  // layer outputs;     cols 133..135 stay 0
__device__ int   g_deg[MAXN];
__device__ int   g_rowptr[MAXN + 1];
__device__ int   g_pos[MAXN];
__device__ int   g_col[MAXE];
__device__ int   g_bsum[256];
__device__ int   g_is64;

// ---------------- prologue: deg=1 (self loop) + dtype detect ----------------
// int64 values < 2^31 -> every odd int32 word is 0. int32 random ids -> not.
__global__ void prologue_kernel(const int* __restrict__ w, int n) {
    int i = blockIdx.x * blockDim.x + threadIdx.x;
    if (i < n) g_deg[i] = 1;
    if (blockIdx.x == 0 && threadIdx.x < 32) {
        int lane = threadIdx.x;
        int bad = 0;
#pragma unroll
        for (int it = 0; it < 32; it++)
            bad |= w[2 * (lane + 32 * it) + 1];
        unsigned any = __ballot_sync(0xffffffffu, bad != 0);
        if (lane == 0) g_is64 = (any == 0u) ? 1 : 0;
    }
}

__device__ __forceinline__ int load_idx(const void* p, long long i) {
    return g_is64 ? (int)((const long long*)p)[i] : ((const int*)p)[i];
}

__global__ void count_deg_kernel(const void* __restrict__ ei, int e) {
    int i = blockIdx.x * blockDim.x + threadIdx.x;
    if (i < e) atomicAdd(&g_deg[load_idx(ei, (long long)e + i)], 1);
}

// ---------------- 2-level parallel exclusive scan of (deg-1) ----------------
__global__ void partial_kernel(int n) {
    __shared__ int wsum[8];
    int i = blockIdx.x * blockDim.x + threadIdx.x;
    int d = (i < n) ? g_deg[i] - 1 : 0;
    int lane = threadIdx.x & 31, wid = threadIdx.x >> 5;
#pragma unroll
    for (int o = 16; o > 0; o >>= 1) d += __shfl_down_sync(0xffffffffu, d, o);
    if (lane == 0) wsum[wid] = d;
    __syncthreads();
    if (wid == 0) {
        int s = (lane < 8) ? wsum[lane] : 0;
#pragma unroll
        for (int o = 4; o > 0; o >>= 1) s += __shfl_down_sync(0xffffffffu, s, o);
        if (lane == 0) g_bsum[blockIdx.x] = s;
    }
}

__global__ void finalize_kernel(int n, int e) {
    __shared__ int wsum[8];
    __shared__ int off_s;
    int tid = threadIdx.x, bid = blockIdx.x;
    int lane = tid & 31, wid = tid >> 5;
    {
        int v = (tid < bid) ? g_bsum[tid] : 0;
#pragma unroll
        for (int o = 16; o > 0; o >>= 1) v += __shfl_down_sync(0xffffffffu, v, o);
        if (lane == 0) wsum[wid] = v;
        __syncthreads();
        if (wid == 0) {
            int s = (lane < 8) ? wsum[lane] : 0;
#pragma unroll
            for (int o = 4; o > 0; o >>= 1) s += __shfl_down_sync(0xffffffffu, s, o);
            if (lane == 0) off_s = s;
        }
        __syncthreads();
    }
    int offset = off_s;
    __syncthreads();

    int i = bid * blockDim.x + tid;
    int deg = (i < n) ? g_deg[i] : 1;
    int d = (i < n) ? deg - 1 : 0;
    int v = d;
#pragma unroll
    for (int o = 1; o < 32; o <<= 1) {
        int t = __shfl_up_sync(0xffffffffu, v, o);
        if (lane >= o) v += t;
    }
    if (lane == 31) wsum[wid] = v;
    __syncthreads();
    if (wid == 0) {
        int s = (lane < 8) ? wsum[lane] : 0;
#pragma unroll
        for (int o = 1; o < 8; o <<= 1) {
            int t = __shfl_up_sync(0xffffffffu, s, o);
            if (lane >= o) s += t;
        }
        if (lane < 8) wsum[lane] = s;
    }
    __syncthreads();
    int excl = v - d + ((wid > 0) ? wsum[wid - 1] : 0);
    if (i < n) {
        int rp = offset + excl;
        g_rowptr[i] = rp;
        g_pos[i] = rp;
    }
    if (i == 0) g_rowptr[n] = e;
}

__global__ void fill_kernel(const void* __restrict__ ei, int e) {
    int i = blockIdx.x * blockDim.x + threadIdx.x;
    if (i < e) {
        int sidx = load_idx(ei, i);
        int d    = load_idx(ei, (long long)e + i);
        g_col[atomicAdd(&g_pos[d], 1)] = sidx;
    }
}

// ---------------- GEMM: g_hp[r][c] = dinv[r] * sum_k X[r][k]*W[k][c] ----------------
// 256 threads/block, 32 rows x 133 cols per block; 4 full K-chunks of 32
// (compile-time, fully unrolled -> immediate LDS offsets) + 5-k tail.
// Thread (warp w, lane l): rows w*4..w*4+3, cols l+32*j (j<5). 20 accumulators.
__global__ void __launch_bounds__(256, 3)
gemm_kernel(const float* __restrict__ Xext, const float* __restrict__ W,
            int use_ext, int n) {
    __shared__ float Ws[32][DNF + 3];                // 17408 B
    __shared__ __align__(16) float Xs[32][36];       // 4608 B; 16B-aligned rows

    const float* X = use_ext ? Xext : (const float*)g_feat;
    int ldx = use_ext ? DNF : DPAD;
    int tid = threadIdx.x;
    int lane = tid & 31, warp = tid >> 5;
    int row0 = blockIdx.x * 32;
    int rbase = warp * 4;                            // 8 warps x 4 rows = 32 rows

    float acc[4][5];
#pragma unroll
    for (int i = 0; i < 4; i++)
#pragma unroll
        for (int j = 0; j < 5; j++) acc[i][j] = 0.f;

    // ---- 4 full chunks of 32 k ----
    for (int c = 0; c < 4; c++) {
        int k0 = c * 32;
        // W fill: warp w rows 4w..4w+3 (division-free, coalesced-ish)
#pragma unroll
        for (int kq = 0; kq < 4; kq++) {
            const float* wrow = W + (size_t)(k0 + rbase + kq) * DNF;
            for (int cc = lane; cc < DNF; cc += 32) Ws[rbase + kq][cc] = wrow[cc];
        }
        // X fill: 32 rows x 32 k, consecutive tid -> consecutive k (coalesced)
#pragma unroll
        for (int q = 0; q < 4; q++) {
            int i = tid + 256 * q;
            int kk = i & 31, r = i >> 5;
            int gr = row0 + r;
            Xs[r][kk] = (gr < n) ? X[(size_t)gr * ldx + k0 + kk] : 0.f;
        }
        __syncthreads();

#pragma unroll
        for (int t = 0; t < 8; t++) {
            float4 a4[4];
#pragma unroll
            for (int i = 0; i < 4; i++)
                a4[i] = *(const float4*)&Xs[rbase + i][4 * t];   // broadcast LDS.128
#pragma unroll
            for (int q = 0; q < 4; q++) {
                float b[5];
#pragma unroll
                for (int j = 0; j < 4; j++) b[j] = Ws[4 * t + q][lane + 32 * j];
                b[4] = (lane < 5) ? Ws[4 * t + q][lane + 128] : 0.f;
#pragma unroll
                for (int i = 0; i < 4; i++) {
                    float a = (q == 0) ? a4[i].x : (q == 1) ? a4[i].y
                            : (q == 2) ? a4[i].z : a4[i].w;
#pragma unroll
                    for (int j = 0; j < 5; j++) acc[i][j] += a * b[j];
                }
            }
        }
        __syncthreads();
    }

    // ---- tail: k = 128..132 (5 steps) ----
    {
        const int k0 = 128;
#pragma unroll
        for (int kq = 0; kq < 4; kq++) {
            int kk = rbase + kq;
            bool kv = (k0 + kk < DNF);                // only kk < 5 valid
            const float* wrow = W + (size_t)(k0 + kk) * DNF;
            for (int cc = lane; cc < DNF; cc += 32) Ws[kk][cc] = kv ? wrow[cc] : 0.f;
        }
#pragma unroll
        for (int q = 0; q < 4; q++) {
            int i = tid + 256 * q;
            int kk = i & 31, r = i >> 5;
            int gr = row0 + r;
            Xs[r][kk] = (kk < 5 && gr < n) ? X[(size_t)gr * ldx + k0 + kk] : 0.f;
        }
        __syncthreads();
#pragma unroll
        for (int kk = 0; kk < 5; kk++) {
            float b[5];
#pragma unroll
            for (int j = 0; j < 4; j++) b[j] = Ws[kk][lane + 32 * j];
            b[4] = (lane < 5) ? Ws[kk][lane + 128] : 0.f;
#pragma unroll
            for (int i = 0; i < 4; i++) {
                float a = Xs[rbase + i][kk];
#pragma unroll
                for (int j = 0; j < 5; j++) acc[i][j] += a * b[j];
            }
        }
    }

    // ---- epilogue ----
#pragma unroll
    for (int i = 0; i < 4; i++) {
        int r = row0 + rbase + i;
        if (r < n) {
            float di = rsqrtf((float)g_deg[r]);
#pragma unroll
            for (int j = 0; j < 5; j++) {
                int c = lane + 32 * j;
                if (c < DNF) g_hp[(size_t)r * DPAD + c] = acc[i][j] * di;
            }
        }
    }
}

// ---------------- aggregate: g_feat[i] = relu(dinv[i]*(sum_in hp[j] + hp[i]) + b) ----------------
// One warp per node; lane owns float4 at col 4*lane; lanes 0..1 own tail float4s.
__global__ void aggregate_kernel(const float* __restrict__ bias, int n) {
    int node = blockIdx.x * (blockDim.x >> 5) + (threadIdx.x >> 5);
    if (node >= n) return;
    int lane = threadIdx.x & 31;

    const float4* self4 = (const float4*)(g_hp + (size_t)node * DPAD);
    float4 acc = self4[lane];
    float4 acct = make_float4(0.f, 0.f, 0.f, 0.f);
    if (lane < 2) acct = self4[32 + lane];

    int s = g_rowptr[node], e = g_rowptr[node + 1];
    int idx = s;
    for (; idx + 1 < e; idx += 2) {
        int j0 = g_col[idx], j1 = g_col[idx + 1];
        const float4* r0 = (const float4*)(g_hp + (size_t)j0 * DPAD);
        const float4* r1 = (const float4*)(g_hp + (size_t)j1 * DPAD);
        float4 v0 = r0[lane];
        float4 v1 = r1[lane];
        float4 t0, t1;
        if (lane < 2) { t0 = r0[32 + lane]; t1 = r1[32 + lane]; }
        acc.x += v0.x; acc.y += v0.y; acc.z += v0.z; acc.w += v0.w;
        acc.x += v1.x; acc.y += v1.y; acc.z += v1.z; acc.w += v1.w;
        if (lane < 2) {
            acct.x += t0.x; acct.y += t0.y; acct.z += t0.z; acct.w += t0.w;
            acct.x += t1.x; acct.y += t1.y; acct.z += t1.z; acct.w += t1.w;
        }
    }
    if (idx < e) {
        int j0 = g_col[idx];
        const float4* r0 = (const float4*)(g_hp + (size_t)j0 * DPAD);
        float4 v0 = r0[lane];
        acc.x += v0.x; acc.y += v0.y; acc.z += v0.z; acc.w += v0.w;
        if (lane < 2) {
            float4 t0 = r0[32 + lane];
            acct.x += t0.x; acct.y += t0.y; acct.z += t0.z; acct.w += t0.w;
        }
    }

    float di = rsqrtf((float)g_deg[node]);
    float4 o;
    o.x = fmaxf(fmaf(acc.x, di, bias[4 * lane + 0]), 0.f);
    o.y = fmaxf(fmaf(acc.y, di, bias[4 * lane + 1]), 0.f);
    o.z = fmaxf(fmaf(acc.z, di, bias[4 * lane + 2]), 0.f);
    o.w = fmaxf(fmaf(acc.w, di, bias[4 * lane + 3]), 0.f);
    float4* out4 = (float4*)(g_feat + (size_t)node * DPAD);
    out4[lane] = o;
    if (lane == 0) {
        float4 t;
        t.x = fmaxf(fmaf(acct.x, di, bias[128]), 0.f);
        t.y = fmaxf(fmaf(acct.y, di, bias[129]), 0.f);
        t.z = fmaxf(fmaf(acct.z, di, bias[130]), 0.f);
        t.w = fmaxf(fmaf(acct.w, di, bias[131]), 0.f);
        out4[32] = t;
    } else if (lane == 1) {
        float4 t;
        t.x = fmaxf(fmaf(acct.x, di, bias[132]), 0.f);
        t.y = 0.f; t.z = 0.f; t.w = 0.f;   // keep pads zero
        out4[33] = t;
    }
}

// ---------------- global mean pool ----------------
__device__ __forceinline__ int lbound_any(const void* a, int n, int v) {
    int lo = 0, hi = n;
    while (lo < hi) {
        int m = (lo + hi) >> 1;
        long long x = g_is64 ? ((const long long*)a)[m]
                             : (long long)((const int*)a)[m];
        if (x < (long long)v) lo = m + 1; else hi = m;
    }
    return lo;
}

__global__ void pool_kernel(const void* __restrict__ batch,
                            float* __restrict__ out, int n) {
    __shared__ int lo_s, hi_s;
    int g = blockIdx.x;
    if (threadIdx.x == 0) {
        lo_s = lbound_any(batch, n, g);
        hi_s = lbound_any(batch, n, g + 1);
    }
    __syncthreads();
    int lo = lo_s, hi = hi_s;
    int c = threadIdx.x;
    if (c < DNF) {
        float s0 = 0.f, s1 = 0.f, s2 = 0.f, s3 = 0.f;
        int r = lo;
        for (; r + 3 < hi; r += 4) {
            s0 += g_feat[(size_t)(r + 0) * DPAD + c];
            s1 += g_feat[(size_t)(r + 1) * DPAD + c];
            s2 += g_feat[(size_t)(r + 2) * DPAD + c];
            s3 += g_feat[(size_t)(r + 3) * DPAD + c];
        }
        for (; r < hi; r++) s0 += g_feat[(size_t)r * DPAD + c];
        int cnt = hi - lo;
        out[g * DNF + c] = ((s0 + s1) + (s2 + s3)) / (float)(cnt > 0 ? cnt : 1);
    }
}

// ---------------- launch: kernel launches ONLY ----------------
extern "C" void kernel_launch(void* const* d_in, const int* in_sizes, int n_in,
                              void* d_out, int out_size) {
    const float* x     = (const float*)d_in[0];
    const void*  ei    = d_in[1];
    const void*  batch = d_in[2];
    const float* W1    = (const float*)d_in[3];
    const float* b1    = (const float*)d_in[4];
    const float* W2    = (const float*)d_in[5];
    const float* b2    = (const float*)d_in[6];
    float* out = (float*)d_out;

    int n = in_sizes[0] / DNF;   // 50000
    int e = in_sizes[1] / 2;     // 800000

    int tb = 256;
    int gn = (n + tb - 1) / tb;  // 196
    int ge = (e + tb - 1) / tb;

    int gemm_blocks = (n + 31) / 32;   // 1563
    int agg_blocks  = (n + 7) / 8;

    prologue_kernel<<<gn, tb>>>((const int*)ei, n);     // 1: deg=1 + dtype detect
    count_deg_kernel<<<ge, tb>>>(ei, e);                // 2
    partial_kernel<<<gn, tb>>>(n);                      // 3
    gemm_kernel<<<gemm_blocks, 256>>>(x, W1, 1, n);     // 4 <- profiled slot
    finalize_kernel<<<gn, tb>>>(n, e);                  // 5: rowptr+pos
    fill_kernel<<<ge, tb>>>(ei, e);                     // 6
    aggregate_kernel<<<agg_blocks, 256>>>(b1, n);       // 7
    gemm_kernel<<<gemm_blocks, 256>>>(x, W2, 0, n);     // 8
    aggregate_kernel<<<agg_blocks, 256>>>(b2, n);       // 9
    pool_kernel<<<NGRAPH, 160>>>(batch, out, n);        // 10
}

// round 10
// speedup vs baseline: 1.3901x; 1.3901x over previous
#include <cuda_runtime.h>
#include <cstdint>

#define DNF  133
#define DPAD 136   // padded feature stride: 544 B rows, float4-aligned
#define MAXN 50000
#define MAXE 800000
#define NGRAPH 256

// ---------------- static device scratch (zero-initialized at load) ----------------
__device__ float g_hp[MAXN * DPAD];    // (X@W) * dinv[row]; cols 133..135 stay 0
__device__ float g_feat[MAXN * DPAD];  // layer outputs;     cols 133..135 stay 0
__device__ int   g_deg[MAXN];
__device__ int   g_rowptr[MAXN + 1];
__device__ int   g_pos[MAXN];
__device__ int   g_col[MAXE];
__device__ int   g_bsum[256];
__device__ int   g_is64;

// ---------------- prologue: deg=1 (self loop) + dtype detect ----------------
// int64 values < 2^31 -> every odd int32 word is 0. int32 random ids -> not.
__global__ void prologue_kernel(const int* __restrict__ w, int n) {
    int i = blockIdx.x * blockDim.x + threadIdx.x;
    if (i < n) g_deg[i] = 1;
    if (blockIdx.x == 0 && threadIdx.x < 32) {
        int lane = threadIdx.x;
        int bad = 0;
#pragma unroll
        for (int it = 0; it < 32; it++)
            bad |= w[2 * (lane + 32 * it) + 1];
        unsigned any = __ballot_sync(0xffffffffu, bad != 0);
        if (lane == 0) g_is64 = (any == 0u) ? 1 : 0;
    }
}

__device__ __forceinline__ int load_idx(const void* p, long long i) {
    return g_is64 ? (int)((const long long*)p)[i] : ((const int*)p)[i];
}

__global__ void count_deg_kernel(const void* __restrict__ ei, int e) {
    int i = blockIdx.x * blockDim.x + threadIdx.x;
    if (i < e) atomicAdd(&g_deg[load_idx(ei, (long long)e + i)], 1);
}

// ---------------- 2-level parallel exclusive scan of (deg-1) ----------------
__global__ void partial_kernel(int n) {
    __shared__ int wsum[8];
    int i = blockIdx.x * blockDim.x + threadIdx.x;
    int d = (i < n) ? g_deg[i] - 1 : 0;
    int lane = threadIdx.x & 31, wid = threadIdx.x >> 5;
#pragma unroll
    for (int o = 16; o > 0; o >>= 1) d += __shfl_down_sync(0xffffffffu, d, o);
    if (lane == 0) wsum[wid] = d;
    __syncthreads();
    if (wid == 0) {
        int s = (lane < 8) ? wsum[lane] : 0;
#pragma unroll
        for (int o = 4; o > 0; o >>= 1) s += __shfl_down_sync(0xffffffffu, s, o);
        if (lane == 0) g_bsum[blockIdx.x] = s;
    }
}

__global__ void finalize_kernel(int n, int e) {
    __shared__ int wsum[8];
    __shared__ int off_s;
    int tid = threadIdx.x, bid = blockIdx.x;
    int lane = tid & 31, wid = tid >> 5;
    {
        int v = (tid < bid) ? g_bsum[tid] : 0;
#pragma unroll
        for (int o = 16; o > 0; o >>= 1) v += __shfl_down_sync(0xffffffffu, v, o);
        if (lane == 0) wsum[wid] = v;
        __syncthreads();
        if (wid == 0) {
            int s = (lane < 8) ? wsum[lane] : 0;
#pragma unroll
            for (int o = 4; o > 0; o >>= 1) s += __shfl_down_sync(0xffffffffu, s, o);
            if (lane == 0) off_s = s;
        }
        __syncthreads();
    }
    int offset = off_s;
    __syncthreads();

    int i = bid * blockDim.x + tid;
    int deg = (i < n) ? g_deg[i] : 1;
    int d = (i < n) ? deg - 1 : 0;
    int v = d;
#pragma unroll
    for (int o = 1; o < 32; o <<= 1) {
        int t = __shfl_up_sync(0xffffffffu, v, o);
        if (lane >= o) v += t;
    }
    if (lane == 31) wsum[wid] = v;
    __syncthreads();
    if (wid == 0) {
        int s = (lane < 8) ? wsum[lane] : 0;
#pragma unroll
        for (int o = 1; o < 8; o <<= 1) {
            int t = __shfl_up_sync(0xffffffffu, s, o);
            if (lane >= o) s += t;
        }
        if (lane < 8) wsum[lane] = s;
    }
    __syncthreads();
    int excl = v - d + ((wid > 0) ? wsum[wid - 1] : 0);
    if (i < n) {
        int rp = offset + excl;
        g_rowptr[i] = rp;
        g_pos[i] = rp;
    }
    if (i == 0) g_rowptr[n] = e;
}

__global__ void fill_kernel(const void* __restrict__ ei, int e) {
    int i = blockIdx.x * blockDim.x + threadIdx.x;
    if (i < e) {
        int sidx = load_idx(ei, i);
        int d    = load_idx(ei, (long long)e + i);
        g_col[atomicAdd(&g_pos[d], 1)] = sidx;
    }
}

// ---------------- GEMM: g_hp[r][c] = dinv[r] * sum_k X[r][k]*W[k][c] ----------------
// 256 threads/block, 64 rows x 133 cols; 4 compile-time K-chunks of 32
// (inner t-loop fully unrolled -> immediate LDS offsets) + 5-k tail.
// Ws padded to 160 cols (zero-filled) so all 5 b-loads are unpredicated.
// Thread (warp w, lane l): rows w*8..w*8+7, cols l+32*j (j<5). 40 accumulators.
__global__ void __launch_bounds__(256)
gemm_kernel(const float* __restrict__ Xext, const float* __restrict__ W,
            int use_ext, int n) {
    __shared__ float Ws[32][160];                    // 20480 B, zero-padded cols
    __shared__ __align__(16) float Xs[64][36];       // 9216 B; 16B-aligned rows

    const float* X = use_ext ? Xext : (const float*)g_feat;
    int ldx = use_ext ? DNF : DPAD;
    int tid = threadIdx.x;
    int lane = tid & 31, warp = tid >> 5;
    int row0 = blockIdx.x * 64;
    int rbase = warp * 8;

    float acc[8][5];
#pragma unroll
    for (int i = 0; i < 8; i++)
#pragma unroll
        for (int j = 0; j < 5; j++) acc[i][j] = 0.f;

    // ---- 4 full chunks of 32 k ----
    for (int c = 0; c < 4; c++) {
        int k0 = c * 32;
        // W fill: warp w rows 4w..4w+3; cols lane+32*q (q<5), zero past DNF
#pragma unroll
        for (int kq = 0; kq < 4; kq++) {
            int kk = warp * 4 + kq;
            const float* wrow = W + (size_t)(k0 + kk) * DNF;
#pragma unroll
            for (int q = 0; q < 5; q++) {
                int cc = lane + 32 * q;
                Ws[kk][cc] = (cc < DNF) ? wrow[cc] : 0.f;
            }
        }
        // X fill: 64 rows x 32 k; consecutive tid -> consecutive k (coalesced)
#pragma unroll
        for (int q = 0; q < 8; q++) {
            int i = tid + 256 * q;
            int kk = i & 31, r = i >> 5;
            int gr = row0 + r;
            Xs[r][kk] = (gr < n) ? X[(size_t)gr * ldx + k0 + kk] : 0.f;
        }
        __syncthreads();

#pragma unroll
        for (int t = 0; t < 8; t++) {
            float4 a4[8];
#pragma unroll
            for (int i = 0; i < 8; i++)
                a4[i] = *(const float4*)&Xs[rbase + i][4 * t];   // broadcast LDS.128
#pragma unroll
            for (int q = 0; q < 4; q++) {
                float b[5];
#pragma unroll
                for (int j = 0; j < 5; j++) b[j] = Ws[4 * t + q][lane + 32 * j];
#pragma unroll
                for (int i = 0; i < 8; i++) {
                    float a = (q == 0) ? a4[i].x : (q == 1) ? a4[i].y
                            : (q == 2) ? a4[i].z : a4[i].w;
#pragma unroll
                    for (int j = 0; j < 5; j++) acc[i][j] += a * b[j];
                }
            }
        }
        __syncthreads();
    }

    // ---- tail: k = 128..132 (5 steps) ----
    {
        const int k0 = 128;
#pragma unroll
        for (int kq = 0; kq < 4; kq++) {
            int kk = warp * 4 + kq;
            bool kv = (k0 + kk < DNF);                // only kk < 5 valid
            const float* wrow = W + (size_t)(k0 + kk) * DNF;
#pragma unroll
            for (int q = 0; q < 5; q++) {
                int cc = lane + 32 * q;
                Ws[kk][cc] = (kv && cc < DNF) ? wrow[cc] : 0.f;
            }
        }
#pragma unroll
        for (int q = 0; q < 8; q++) {
            int i = tid + 256 * q;
            int kk = i & 31, r = i >> 5;
            int gr = row0 + r;
            Xs[r][kk] = (kk < 5 && gr < n) ? X[(size_t)gr * ldx + k0 + kk] : 0.f;
        }
        __syncthreads();
#pragma unroll
        for (int kk = 0; kk < 5; kk++) {
            float b[5];
#pragma unroll
            for (int j = 0; j < 5; j++) b[j] = Ws[kk][lane + 32 * j];
#pragma unroll
            for (int i = 0; i < 8; i++) {
                float a = Xs[rbase + i][kk];
#pragma unroll
                for (int j = 0; j < 5; j++) acc[i][j] += a * b[j];
            }
        }
    }

    // ---- epilogue: scale by dinv, store ----
#pragma unroll
    for (int i = 0; i < 8; i++) {
        int r = row0 + rbase + i;
        if (r < n) {
            float di = rsqrtf((float)g_deg[r]);
#pragma unroll
            for (int j = 0; j < 5; j++) {
                int c = lane + 32 * j;
                if (c < DNF) g_hp[(size_t)r * DPAD + c] = acc[i][j] * di;
            }
        }
    }
}

// ---------------- aggregate: g_feat[i] = relu(dinv[i]*(sum_in hp[j] + hp[i]) + b) ----------------
// One warp per node; lane owns float4 at col 4*lane; lanes 0..1 own tail float4s.
__global__ void aggregate_kernel(const float* __restrict__ bias, int n) {
    int node = blockIdx.x * (blockDim.x >> 5) + (threadIdx.x >> 5);
    if (node >= n) return;
    int lane = threadIdx.x & 31;

    const float4* self4 = (const float4*)(g_hp + (size_t)node * DPAD);
    float4 acc = self4[lane];
    float4 acct = make_float4(0.f, 0.f, 0.f, 0.f);
    if (lane < 2) acct = self4[32 + lane];

    int s = g_rowptr[node], e = g_rowptr[node + 1];
    int idx = s;
    for (; idx + 1 < e; idx += 2) {
        int j0 = g_col[idx], j1 = g_col[idx + 1];
        const float4* r0 = (const float4*)(g_hp + (size_t)j0 * DPAD);
        const float4* r1 = (const float4*)(g_hp + (size_t)j1 * DPAD);
        float4 v0 = r0[lane];
        float4 v1 = r1[lane];
        float4 t0, t1;
        if (lane < 2) { t0 = r0[32 + lane]; t1 = r1[32 + lane]; }
        acc.x += v0.x; acc.y += v0.y; acc.z += v0.z; acc.w += v0.w;
        acc.x += v1.x; acc.y += v1.y; acc.z += v1.z; acc.w += v1.w;
        if (lane < 2) {
            acct.x += t0.x; acct.y += t0.y; acct.z += t0.z; acct.w += t0.w;
            acct.x += t1.x; acct.y += t1.y; acct.z += t1.z; acct.w += t1.w;
        }
    }
    if (idx < e) {
        int j0 = g_col[idx];
        const float4* r0 = (const float4*)(g_hp + (size_t)j0 * DPAD);
        float4 v0 = r0[lane];
        acc.x += v0.x; acc.y += v0.y; acc.z += v0.z; acc.w += v0.w;
        if (lane < 2) {
            float4 t0 = r0[32 + lane];
            acct.x += t0.x; acct.y += t0.y; acct.z += t0.z; acct.w += t0.w;
        }
    }

    float di = rsqrtf((float)g_deg[node]);
    float4 o;
    o.x = fmaxf(fmaf(acc.x, di, bias[4 * lane + 0]), 0.f);
    o.y = fmaxf(fmaf(acc.y, di, bias[4 * lane + 1]), 0.f);
    o.z = fmaxf(fmaf(acc.z, di, bias[4 * lane + 2]), 0.f);
    o.w = fmaxf(fmaf(acc.w, di, bias[4 * lane + 3]), 0.f);
    float4* out4 = (float4*)(g_feat + (size_t)node * DPAD);
    out4[lane] = o;
    if (lane == 0) {
        float4 t;
        t.x = fmaxf(fmaf(acct.x, di, bias[128]), 0.f);
        t.y = fmaxf(fmaf(acct.y, di, bias[129]), 0.f);
        t.z = fmaxf(fmaf(acct.z, di, bias[130]), 0.f);
        t.w = fmaxf(fmaf(acct.w, di, bias[131]), 0.f);
        out4[32] = t;
    } else if (lane == 1) {
        float4 t;
        t.x = fmaxf(fmaf(acct.x, di, bias[132]), 0.f);
        t.y = 0.f; t.z = 0.f; t.w = 0.f;   // keep pads zero
        out4[33] = t;
    }
}

// ---------------- global mean pool ----------------
__device__ __forceinline__ int lbound_any(const void* a, int n, int v) {
    int lo = 0, hi = n;
    while (lo < hi) {
        int m = (lo + hi) >> 1;
        long long x = g_is64 ? ((const long long*)a)[m]
                             : (long long)((const int*)a)[m];
        if (x < (long long)v) lo = m + 1; else hi = m;
    }
    return lo;
}

__global__ void pool_kernel(const void* __restrict__ batch,
                            float* __restrict__ out, int n) {
    __shared__ int lo_s, hi_s;
    int g = blockIdx.x;
    if (threadIdx.x == 0) {
        lo_s = lbound_any(batch, n, g);
        hi_s = lbound_any(batch, n, g + 1);
    }
    __syncthreads();
    int lo = lo_s, hi = hi_s;
    int c = threadIdx.x;
    if (c < DNF) {
        float s0 = 0.f, s1 = 0.f, s2 = 0.f, s3 = 0.f;
        int r = lo;
        for (; r + 3 < hi; r += 4) {
            s0 += g_feat[(size_t)(r + 0) * DPAD + c];
            s1 += g_feat[(size_t)(r + 1) * DPAD + c];
            s2 += g_feat[(size_t)(r + 2) * DPAD + c];
            s3 += g_feat[(size_t)(r + 3) * DPAD + c];
        }
        for (; r < hi; r++) s0 += g_feat[(size_t)r * DPAD + c];
        int cnt = hi - lo;
        out[g * DNF + c] = ((s0 + s1) + (s2 + s3)) / (float)(cnt > 0 ? cnt : 1);
    }
}

// ---------------- launch: kernel launches ONLY ----------------
extern "C" void kernel_launch(void* const* d_in, const int* in_sizes, int n_in,
                              void* d_out, int out_size) {
    const float* x     = (const float*)d_in[0];
    const void*  ei    = d_in[1];
    const void*  batch = d_in[2];
    const float* W1    = (const float*)d_in[3];
    const float* b1    = (const float*)d_in[4];
    const float* W2    = (const float*)d_in[5];
    const float* b2    = (const float*)d_in[6];
    float* out = (float*)d_out;

    int n = in_sizes[0] / DNF;   // 50000
    int e = in_sizes[1] / 2;     // 800000

    int tb = 256;
    int gn = (n + tb - 1) / tb;  // 196
    int ge = (e + tb - 1) / tb;

    int gemm_blocks = (n + 63) / 64;   // 782
    int agg_blocks  = (n + 7) / 8;

    prologue_kernel<<<gn, tb>>>((const int*)ei, n);     // 1: deg=1 + dtype detect
    count_deg_kernel<<<ge, tb>>>(ei, e);                // 2
    partial_kernel<<<gn, tb>>>(n);                      // 3
    gemm_kernel<<<gemm_blocks, 256>>>(x, W1, 1, n);     // 4 <- profiled slot
    finalize_kernel<<<gn, tb>>>(n, e);                  // 5: rowptr+pos
    fill_kernel<<<ge, tb>>>(ei, e);                     // 6
    aggregate_kernel<<<agg_blocks, 256>>>(b1, n);       // 7
    gemm_kernel<<<gemm_blocks, 256>>>(x, W2, 0, n);     // 8
    aggregate_kernel<<<agg_blocks, 256>>>(b2, n);       // 9
    pool_kernel<<<NGRAPH, 160>>>(batch, out, n);        // 10
}

// round 11
// speedup vs baseline: 1.4815x; 1.0658x over previous
#include <cuda_runtime.h>
#include <cstdint>

#define DNF  133
#define DPAD 136   // padded feature stride: 544 B rows, float4-aligned
#define MAXN 50000
#define MAXE 800000
#define NGRAPH 256
#define WDIM 136   // padded W dim for mma (17 n-tiles of 8, 17 k-steps of 8)

// ---------------- static device scratch (zero-initialized at load) ----------------
__device__ float g_hp[MAXN * DPAD];    // (X@W) * dinv[row]; cols 133..135 stay 0
__device__ float g_feat[MAXN * DPAD];  // layer outputs;     cols 133..135 stay 0
__device__ int   g_deg[MAXN];
__device__ int   g_rowptr[MAXN + 1];
__device__ int   g_pos[MAXN];
__device__ int   g_col[MAXE];
__device__ int   g_bsum[256];
__device__ int   g_is64;
// W split into tf32 hi/lo planes, [k][n] layout, n contiguous, zero-padded
__device__ float g_Whi[2][WDIM * WDIM];
__device__ float g_Wlo[2][WDIM * WDIM];

// ---------------- tf32 helpers ----------------
__device__ __forceinline__ uint32_t f2tf32(float f) {
    uint32_t u;
    asm("cvt.rna.tf32.f32 %0, %1;" : "=r"(u) : "f"(f));
    return u;
}
// D(16x8,f32) += A(16x8,tf32,row) * B(8x8,tf32,col)
#define MMA_TF32(d, a, b0, b1) \
    asm("mma.sync.aligned.m16n8k8.row.col.f32.tf32.tf32.f32 " \
        "{%0,%1,%2,%3}, {%4,%5,%6,%7}, {%8,%9}, {%0,%1,%2,%3};" \
        : "+f"((d)[0]), "+f"((d)[1]), "+f"((d)[2]), "+f"((d)[3]) \
        : "r"((a)[0]), "r"((a)[1]), "r"((a)[2]), "r"((a)[3]), "r"(b0), "r"(b1))

// ---------------- prologue: deg=1 (self loop) + dtype detect ----------------
// int64 values < 2^31 -> every odd int32 word is 0. int32 random ids -> not.
__global__ void prologue_kernel(const int* __restrict__ w, int n) {
    int i = blockIdx.x * blockDim.x + threadIdx.x;
    if (i < n) g_deg[i] = 1;
    if (blockIdx.x == 0 && threadIdx.x < 32) {
        int lane = threadIdx.x;
        int bad = 0;
#pragma unroll
        for (int it = 0; it < 32; it++)
            bad |= w[2 * (lane + 32 * it) + 1];
        unsigned any = __ballot_sync(0xffffffffu, bad != 0);
        if (lane == 0) g_is64 = (any == 0u) ? 1 : 0;
    }
}

__device__ __forceinline__ int load_idx(const void* p, long long i) {
    return g_is64 ? (int)((const long long*)p)[i] : ((const int*)p)[i];
}

__global__ void count_deg_kernel(const void* __restrict__ ei, int e) {
    int i = blockIdx.x * blockDim.x + threadIdx.x;
    if (i < e) atomicAdd(&g_deg[load_idx(ei, (long long)e + i)], 1);
}

// ---------------- W split: g_Whi/g_Wlo[w][k][n] (tf32 hi/lo of W[k][n]) ----------------
// grid (WDIM, 2), 160 threads; thread tid = n.
__global__ void wconv_kernel(const float* __restrict__ W1,
                             const float* __restrict__ W2) {
    int k = blockIdx.x, w = blockIdx.y, nn = threadIdx.x;
    if (nn >= WDIM) return;
    const float* W = w ? W2 : W1;
    float v = (k < DNF && nn < DNF) ? W[k * DNF + nn] : 0.f;
    uint32_t uh = f2tf32(v);
    float vh = __uint_as_float(uh);
    uint32_t ul = f2tf32(v - vh);
    g_Whi[w][k * WDIM + nn] = vh;
    g_Wlo[w][k * WDIM + nn] = __uint_as_float(ul);
}

// ---------------- 2-level parallel exclusive scan of (deg-1) ----------------
__global__ void partial_kernel(int n) {
    __shared__ int wsum[8];
    int i = blockIdx.x * blockDim.x + threadIdx.x;
    int d = (i < n) ? g_deg[i] - 1 : 0;
    int lane = threadIdx.x & 31, wid = threadIdx.x >> 5;
#pragma unroll
    for (int o = 16; o > 0; o >>= 1) d += __shfl_down_sync(0xffffffffu, d, o);
    if (lane == 0) wsum[wid] = d;
    __syncthreads();
    if (wid == 0) {
        int s = (lane < 8) ? wsum[lane] : 0;
#pragma unroll
        for (int o = 4; o > 0; o >>= 1) s += __shfl_down_sync(0xffffffffu, s, o);
        if (lane == 0) g_bsum[blockIdx.x] = s;
    }
}

__global__ void finalize_kernel(int n, int e) {
    __shared__ int wsum[8];
    __shared__ int off_s;
    int tid = threadIdx.x, bid = blockIdx.x;
    int lane = tid & 31, wid = tid >> 5;
    {
        int v = (tid < bid) ? g_bsum[tid] : 0;
#pragma unroll
        for (int o = 16; o > 0; o >>= 1) v += __shfl_down_sync(0xffffffffu, v, o);
        if (lane == 0) wsum[wid] = v;
        __syncthreads();
        if (wid == 0) {
            int s = (lane < 8) ? wsum[lane] : 0;
#pragma unroll
            for (int o = 4; o > 0; o >>= 1) s += __shfl_down_sync(0xffffffffu, s, o);
            if (lane == 0) off_s = s;
        }
        __syncthreads();
    }
    int offset = off_s;
    __syncthreads();

    int i = bid * blockDim.x + tid;
    int deg = (i < n) ? g_deg[i] : 1;
    int d = (i < n) ? deg - 1 : 0;
    int v = d;
#pragma unroll
    for (int o = 1; o < 32; o <<= 1) {
        int t = __shfl_up_sync(0xffffffffu, v, o);
        if (lane >= o) v += t;
    }
    if (lane == 31) wsum[wid] = v;
    __syncthreads();
    if (wid == 0) {
        int s = (lane < 8) ? wsum[lane] : 0;
#pragma unroll
        for (int o = 1; o < 8; o <<= 1) {
            int t = __shfl_up_sync(0xffffffffu, s, o);
            if (lane >= o) s += t;
        }
        if (lane < 8) wsum[lane] = s;
    }
    __syncthreads();
    int excl = v - d + ((wid > 0) ? wsum[wid - 1] : 0);
    if (i < n) {
        int rp = offset + excl;
        g_rowptr[i] = rp;
        g_pos[i] = rp;
    }
    if (i == 0) g_rowptr[n] = e;
}

__global__ void fill_kernel(const void* __restrict__ ei, int e) {
    int i = blockIdx.x * blockDim.x + threadIdx.x;
    if (i < e) {
        int sidx = load_idx(ei, i);
        int d    = load_idx(ei, (long long)e + i);
        g_col[atomicAdd(&g_pos[d], 1)] = sidx;
    }
}

// ---------------- tensor-core GEMM (tf32 split): g_hp = dinv .* (X @ W) ----------------
// Block: 256 threads = 8 warps, 128 rows x 136 cols. Warp = 16-row strip.
// Split tf32: X = xh + xl, W = wh + wl; acc += xh*wh + xh*wl + xl*wh.
// K: 9 chunks of 16 (144 >= 136, zero-padded).
__global__ void __launch_bounds__(256)
gemm_mma_kernel(const float* __restrict__ Xext, int widx, int use_ext, int n) {
    __shared__ float Xs[128][20];        // stride 20 -> A-frag loads conflict-free
    __shared__ float Whs[16][WDIM];      // k-major W hi plane chunk
    __shared__ float Wls[16][WDIM];      // lo plane

    const float* X = use_ext ? Xext : (const float*)g_feat;
    int ldx = use_ext ? DNF : DPAD;
    const float* Whi = g_Whi[widx];
    const float* Wlo = g_Wlo[widx];

    int tid = threadIdx.x;
    int lane = tid & 31, warp = tid >> 5;
    int row0 = blockIdx.x * 128;
    int strip = warp * 16;
    int gid = lane >> 2;    // 0..7
    int tig = lane & 3;     // 0..3

    float acc[17][4];
#pragma unroll
    for (int t = 0; t < 17; t++)
#pragma unroll
        for (int j = 0; j < 4; j++) acc[t][j] = 0.f;

    for (int ch = 0; ch < 9; ch++) {
        int k0 = ch * 16;
        // ---- fill Xs: 128 rows x 16 k ----
#pragma unroll
        for (int q = 0; q < 8; q++) {
            int i = tid + 256 * q;
            int r = i >> 4, c = i & 15;
            int gr = row0 + r, k = k0 + c;
            Xs[r][c] = (gr < n && k < DNF) ? X[(size_t)gr * ldx + k] : 0.f;
        }
        // ---- fill W planes: warp w rows {2w, 2w+1} ----
#pragma unroll
        for (int rr = 0; rr < 2; rr++) {
            int kk = warp * 2 + rr;
            int k = k0 + kk;
            bool kv = (k < WDIM);
            const float* wh = Whi + (size_t)(kv ? k : 0) * WDIM;
            const float* wl = Wlo + (size_t)(kv ? k : 0) * WDIM;
#pragma unroll
            for (int q = 0; q < 5; q++) {
                int cc = lane + 32 * q;
                if (cc < WDIM) {
                    Whs[kk][cc] = kv ? wh[cc] : 0.f;
                    Wls[kk][cc] = kv ? wl[cc] : 0.f;
                }
            }
        }
        __syncthreads();

        // ---- 2 k-steps of 8 ----
#pragma unroll
        for (int ks = 0; ks < 2; ks++) {
            int kb = ks * 8;
            // A fragments (rows warp-exclusive): load fp32, split to tf32 hi/lo
            float x00 = Xs[strip + gid][kb + tig];
            float x10 = Xs[strip + gid + 8][kb + tig];
            float x01 = Xs[strip + gid][kb + tig + 4];
            float x11 = Xs[strip + gid + 8][kb + tig + 4];
            uint32_t ah[4], al[4];
            ah[0] = f2tf32(x00); al[0] = f2tf32(x00 - __uint_as_float(ah[0]));
            ah[1] = f2tf32(x10); al[1] = f2tf32(x10 - __uint_as_float(ah[1]));
            ah[2] = f2tf32(x01); al[2] = f2tf32(x01 - __uint_as_float(ah[2]));
            ah[3] = f2tf32(x11); al[3] = f2tf32(x11 - __uint_as_float(ah[3]));

#pragma unroll
            for (int nt = 0; nt < 17; nt++) {
                int nb = nt * 8 + gid;
                uint32_t bh0 = __float_as_uint(Whs[kb + tig][nb]);
                uint32_t bh1 = __float_as_uint(Whs[kb + tig + 4][nb]);
                uint32_t bl0 = __float_as_uint(Wls[kb + tig][nb]);
                uint32_t bl1 = __float_as_uint(Wls[kb + tig + 4][nb]);
                MMA_TF32(acc[nt], ah, bh0, bh1);
                MMA_TF32(acc[nt], ah, bl0, bl1);
                MMA_TF32(acc[nt], al, bh0, bh1);
            }
        }
        __syncthreads();
    }

    // ---- epilogue: D thread layout (gid, 2*tig),(.,+1),(gid+8, 2*tig),(.,+1) ----
    int r0 = row0 + strip + gid;
    int r1 = r0 + 8;
    float d0 = (r0 < n) ? rsqrtf((float)g_deg[r0]) : 0.f;
    float d1 = (r1 < n) ? rsqrtf((float)g_deg[r1]) : 0.f;
#pragma unroll
    for (int nt = 0; nt < 17; nt++) {
        int c0 = nt * 8 + 2 * tig;
        if (r0 < n)
            *(float2*)(g_hp + (size_t)r0 * DPAD + c0) =
                make_float2(acc[nt][0] * d0, acc[nt][1] * d0);
        if (r1 < n)
            *(float2*)(g_hp + (size_t)r1 * DPAD + c0) =
                make_float2(acc[nt][2] * d1, acc[nt][3] * d1);
    }
}

// ---------------- aggregate: g_feat[i] = relu(dinv[i]*(sum_in hp[j] + hp[i]) + b) ----------------
// One warp per node; lane owns float4 at col 4*lane; lanes 0..1 own tail float4s.
__global__ void aggregate_kernel(const float* __restrict__ bias, int n) {
    int node = blockIdx.x * (blockDim.x >> 5) + (threadIdx.x >> 5);
    if (node >= n) return;
    int lane = threadIdx.x & 31;

    const float4* self4 = (const float4*)(g_hp + (size_t)node * DPAD);
    float4 acc = self4[lane];
    float4 acct = make_float4(0.f, 0.f, 0.f, 0.f);
    if (lane < 2) acct = self4[32 + lane];

    int s = g_rowptr[node], e = g_rowptr[node + 1];
    int idx = s;
    for (; idx + 1 < e; idx += 2) {
        int j0 = g_col[idx], j1 = g_col[idx + 1];
        const float4* r0 = (const float4*)(g_hp + (size_t)j0 * DPAD);
        const float4* r1 = (const float4*)(g_hp + (size_t)j1 * DPAD);
        float4 v0 = r0[lane];
        float4 v1 = r1[lane];
        float4 t0, t1;
        if (lane < 2) { t0 = r0[32 + lane]; t1 = r1[32 + lane]; }
        acc.x += v0.x; acc.y += v0.y; acc.z += v0.z; acc.w += v0.w;
        acc.x += v1.x; acc.y += v1.y; acc.z += v1.z; acc.w += v1.w;
        if (lane < 2) {
            acct.x += t0.x; acct.y += t0.y; acct.z += t0.z; acct.w += t0.w;
            acct.x += t1.x; acct.y += t1.y; acct.z += t1.z; acct.w += t1.w;
        }
    }
    if (idx < e) {
        int j0 = g_col[idx];
        const float4* r0 = (const float4*)(g_hp + (size_t)j0 * DPAD);
        float4 v0 = r0[lane];
        acc.x += v0.x; acc.y += v0.y; acc.z += v0.z; acc.w += v0.w;
        if (lane < 2) {
            float4 t0 = r0[32 + lane];
            acct.x += t0.x; acct.y += t0.y; acct.z += t0.z; acct.w += t0.w;
        }
    }

    float di = rsqrtf((float)g_deg[node]);
    float4 o;
    o.x = fmaxf(fmaf(acc.x, di, bias[4 * lane + 0]), 0.f);
    o.y = fmaxf(fmaf(acc.y, di, bias[4 * lane + 1]), 0.f);
    o.z = fmaxf(fmaf(acc.z, di, bias[4 * lane + 2]), 0.f);
    o.w = fmaxf(fmaf(acc.w, di, bias[4 * lane + 3]), 0.f);
    float4* out4 = (float4*)(g_feat + (size_t)node * DPAD);
    out4[lane] = o;
    if (lane == 0) {
        float4 t;
        t.x = fmaxf(fmaf(acct.x, di, bias[128]), 0.f);
        t.y = fmaxf(fmaf(acct.y, di, bias[129]), 0.f);
        t.z = fmaxf(fmaf(acct.z, di, bias[130]), 0.f);
        t.w = fmaxf(fmaf(acct.w, di, bias[131]), 0.f);
        out4[32] = t;
    } else if (lane == 1) {
        float4 t;
        t.x = fmaxf(fmaf(acct.x, di, bias[132]), 0.f);
        t.y = 0.f; t.z = 0.f; t.w = 0.f;   // keep pads zero
        out4[33] = t;
    }
}

// ---------------- global mean pool ----------------
__device__ __forceinline__ int lbound_any(const void* a, int n, int v) {
    int lo = 0, hi = n;
    while (lo < hi) {
        int m = (lo + hi) >> 1;
        long long x = g_is64 ? ((const long long*)a)[m]
                             : (long long)((const int*)a)[m];
        if (x < (long long)v) lo = m + 1; else hi = m;
    }
    return lo;
}

__global__ void pool_kernel(const void* __restrict__ batch,
                            float* __restrict__ out, int n) {
    __shared__ int lo_s, hi_s;
    int g = blockIdx.x;
    if (threadIdx.x == 0) {
        lo_s = lbound_any(batch, n, g);
        hi_s = lbound_any(batch, n, g + 1);
    }
    __syncthreads();
    int lo = lo_s, hi = hi_s;
    int c = threadIdx.x;
    if (c < DNF) {
        float s0 = 0.f, s1 = 0.f, s2 = 0.f, s3 = 0.f;
        int r = lo;
        for (; r + 3 < hi; r += 4) {
            s0 += g_feat[(size_t)(r + 0) * DPAD + c];
            s1 += g_feat[(size_t)(r + 1) * DPAD + c];
            s2 += g_feat[(size_t)(r + 2) * DPAD + c];
            s3 += g_feat[(size_t)(r + 3) * DPAD + c];
        }
        for (; r < hi; r++) s0 += g_feat[(size_t)r * DPAD + c];
        int cnt = hi - lo;
        out[g * DNF + c] = ((s0 + s1) + (s2 + s3)) / (float)(cnt > 0 ? cnt : 1);
    }
}

// ---------------- launch: kernel launches ONLY ----------------
extern "C" void kernel_launch(void* const* d_in, const int* in_sizes, int n_in,
                              void* d_out, int out_size) {
    const float* x     = (const float*)d_in[0];
    const void*  ei    = d_in[1];
    const void*  batch = d_in[2];
    const float* W1    = (const float*)d_in[3];
    const float* b1    = (const float*)d_in[4];
    const float* W2    = (const float*)d_in[5];
    const float* b2    = (const float*)d_in[6];
    float* out = (float*)d_out;

    int n = in_sizes[0] / DNF;   // 50000
    int e = in_sizes[1] / 2;     // 800000

    int tb = 256;
    int gn = (n + tb - 1) / tb;  // 196
    int ge = (e + tb - 1) / tb;

    int gemm_blocks = (n + 127) / 128;   // 391
    int agg_blocks  = (n + 7) / 8;

    prologue_kernel<<<gn, tb>>>((const int*)ei, n);       // 1: deg=1 + dtype detect
    count_deg_kernel<<<ge, tb>>>(ei, e);                  // 2
    wconv_kernel<<<dim3(WDIM, 2), 160>>>(W1, W2);         // 3: tf32 hi/lo split
    gemm_mma_kernel<<<gemm_blocks, 256>>>(x, 0, 1, n);    // 4 <- profiled slot
    partial_kernel<<<gn, tb>>>(n);                        // 5
    finalize_kernel<<<gn, tb>>>(n, e);                    // 6: rowptr+pos
    fill_kernel<<<ge, tb>>>(ei, e);                       // 7
    aggregate_kernel<<<agg_blocks, 256>>>(b1, n);         // 8
    gemm_mma_kernel<<<gemm_blocks, 256>>>(x, 1, 0, n);    // 9
    aggregate_kernel<<<agg_blocks, 256>>>(b2, n);         // 10
    pool_kernel<<<NGRAPH, 160>>>(batch, out, n);          // 11
}

// round 12
// speedup vs baseline: 1.7538x; 1.1837x over previous
#include <cuda_runtime.h>
#include <cstdint>

#define DNF  133
#define DPAD 136   // padded feature stride: 544 B rows, float4-aligned
#define MAXN 50000
#define MAXE 800000
#define NGRAPH 256
#define WDIM 136   // padded W dim for mma (17 n-tiles of 8, 17 k-steps of 8)

// ---------------- static device scratch (zero-initialized at load) ----------------
__device__ float g_hp[MAXN * DPAD];    // (X@W) * dinv[row]; cols 133..135 stay 0
__device__ float g_feat[MAXN * DPAD];  // layer outputs;     cols 133..135 stay 0
__device__ int   g_deg[MAXN];
__device__ int   g_rowptr[MAXN + 1];
__device__ int   g_pos[MAXN];
__device__ int   g_col[MAXE];
__device__ int   g_bsum[256];
__device__ int   g_is64;
// W split into tf32 hi/lo planes, [k][n] layout, n contiguous, zero-padded
__device__ float g_Whi[2][WDIM * WDIM];
__device__ float g_Wlo[2][WDIM * WDIM];

// ---------------- tf32 helpers ----------------
__device__ __forceinline__ uint32_t f2tf32(float f) {
    uint32_t u;
    asm("cvt.rna.tf32.f32 %0, %1;" : "=r"(u) : "f"(f));
    return u;
}
// D(16x8,f32) += A(16x8,tf32,row) * B(8x8,tf32,col)
#define MMA_TF32(d, a, b0, b1) \
    asm("mma.sync.aligned.m16n8k8.row.col.f32.tf32.tf32.f32 " \
        "{%0,%1,%2,%3}, {%4,%5,%6,%7}, {%8,%9}, {%0,%1,%2,%3};" \
        : "+f"((d)[0]), "+f"((d)[1]), "+f"((d)[2]), "+f"((d)[3]) \
        : "r"((a)[0]), "r"((a)[1]), "r"((a)[2]), "r"((a)[3]), "r"(b0), "r"(b1))

// ---------------- prologue: deg=1 (self loop) + dtype detect ----------------
// int64 values < 2^31 -> every odd int32 word is 0. int32 random ids -> not.
__global__ void prologue_kernel(const int* __restrict__ w, int n) {
    int i = blockIdx.x * blockDim.x + threadIdx.x;
    if (i < n) g_deg[i] = 1;
    if (blockIdx.x == 0 && threadIdx.x < 32) {
        int lane = threadIdx.x;
        int bad = 0;
#pragma unroll
        for (int it = 0; it < 32; it++)
            bad |= w[2 * (lane + 32 * it) + 1];
        unsigned any = __ballot_sync(0xffffffffu, bad != 0);
        if (lane == 0) g_is64 = (any == 0u) ? 1 : 0;
    }
}

__device__ __forceinline__ int load_idx(const void* p, long long i) {
    return g_is64 ? (int)((const long long*)p)[i] : ((const int*)p)[i];
}

__global__ void count_deg_kernel(const void* __restrict__ ei, int e) {
    int i = blockIdx.x * blockDim.x + threadIdx.x;
    if (i < e) atomicAdd(&g_deg[load_idx(ei, (long long)e + i)], 1);
}

// ---------------- W split: g_Whi/g_Wlo[w][k][n] (tf32 hi/lo of W[k][n]) ----------------
__global__ void wconv_kernel(const float* __restrict__ W1,
                             const float* __restrict__ W2) {
    int k = blockIdx.x, w = blockIdx.y, nn = threadIdx.x;
    if (nn >= WDIM) return;
    const float* W = w ? W2 : W1;
    float v = (k < DNF && nn < DNF) ? W[k * DNF + nn] : 0.f;
    uint32_t uh = f2tf32(v);
    float vh = __uint_as_float(uh);
    uint32_t ul = f2tf32(v - vh);
    g_Whi[w][k * WDIM + nn] = vh;
    g_Wlo[w][k * WDIM + nn] = __uint_as_float(ul);
}

// ---------------- 2-level parallel exclusive scan of (deg-1) ----------------
__global__ void partial_kernel(int n) {
    __shared__ int wsum[8];
    int i = blockIdx.x * blockDim.x + threadIdx.x;
    int d = (i < n) ? g_deg[i] - 1 : 0;
    int lane = threadIdx.x & 31, wid = threadIdx.x >> 5;
#pragma unroll
    for (int o = 16; o > 0; o >>= 1) d += __shfl_down_sync(0xffffffffu, d, o);
    if (lane == 0) wsum[wid] = d;
    __syncthreads();
    if (wid == 0) {
        int s = (lane < 8) ? wsum[lane] : 0;
#pragma unroll
        for (int o = 4; o > 0; o >>= 1) s += __shfl_down_sync(0xffffffffu, s, o);
        if (lane == 0) g_bsum[blockIdx.x] = s;
    }
}

__global__ void finalize_kernel(int n, int e) {
    __shared__ int wsum[8];
    __shared__ int off_s;
    int tid = threadIdx.x, bid = blockIdx.x;
    int lane = tid & 31, wid = tid >> 5;
    {
        int v = (tid < bid) ? g_bsum[tid] : 0;
#pragma unroll
        for (int o = 16; o > 0; o >>= 1) v += __shfl_down_sync(0xffffffffu, v, o);
        if (lane == 0) wsum[wid] = v;
        __syncthreads();
        if (wid == 0) {
            int s = (lane < 8) ? wsum[lane] : 0;
#pragma unroll
            for (int o = 4; o > 0; o >>= 1) s += __shfl_down_sync(0xffffffffu, s, o);
            if (lane == 0) off_s = s;
        }
        __syncthreads();
    }
    int offset = off_s;
    __syncthreads();

    int i = bid * blockDim.x + tid;
    int deg = (i < n) ? g_deg[i] : 1;
    int d = (i < n) ? deg - 1 : 0;
    int v = d;
#pragma unroll
    for (int o = 1; o < 32; o <<= 1) {
        int t = __shfl_up_sync(0xffffffffu, v, o);
        if (lane >= o) v += t;
    }
    if (lane == 31) wsum[wid] = v;
    __syncthreads();
    if (wid == 0) {
        int s = (lane < 8) ? wsum[lane] : 0;
#pragma unroll
        for (int o = 1; o < 8; o <<= 1) {
            int t = __shfl_up_sync(0xffffffffu, s, o);
            if (lane >= o) s += t;
        }
        if (lane < 8) wsum[lane] = s;
    }
    __syncthreads();
    int excl = v - d + ((wid > 0) ? wsum[wid - 1] : 0);
    if (i < n) {
        int rp = offset + excl;
        g_rowptr[i] = rp;
        g_pos[i] = rp;
    }
    if (i == 0) g_rowptr[n] = e;
}

__global__ void fill_kernel(const void* __restrict__ ei, int e) {
    int i = blockIdx.x * blockDim.x + threadIdx.x;
    if (i < e) {
        int sidx = load_idx(ei, i);
        int d    = load_idx(ei, (long long)e + i);
        g_col[atomicAdd(&g_pos[d], 1)] = sidx;
    }
}

// ---------------- tensor-core GEMM (tf32 split, reg-prefetch pipelined) ----------------
// Block: 256 threads = 8 warps, 128 rows x 136 cols. Warp = 16-row strip.
// Split tf32: acc += xh*wh + xh*wl + xl*wh. K: 9 chunks of 16 (zero-padded).
// Pipeline: chunk ch+1 loads issue BEFORE chunk ch's MMAs; scoreboard wait
// lands at next iteration's smem store, hidden behind tensor work.
__global__ void __launch_bounds__(256)
gemm_mma_kernel(const float* __restrict__ Xext, int widx, int use_ext, int n) {
    __shared__ float Xs[128][20];        // stride 20 -> A-frag loads conflict-free
    __shared__ float Whs[16][WDIM];      // k-major W hi plane chunk
    __shared__ float Wls[16][WDIM];      // lo plane

    const float* X = use_ext ? Xext : (const float*)g_feat;
    int ldx = use_ext ? DNF : DPAD;
    const float* Whi = g_Whi[widx];
    const float* Wlo = g_Wlo[widx];

    int tid = threadIdx.x;
    int lane = tid & 31, warp = tid >> 5;
    int row0 = blockIdx.x * 128;
    int strip = warp * 16;
    int gid = lane >> 2;    // 0..7
    int tig = lane & 3;     // 0..3

    float acc[17][4];
#pragma unroll
    for (int t = 0; t < 17; t++)
#pragma unroll
        for (int j = 0; j < 4; j++) acc[t][j] = 0.f;

    // prefetch registers
    float xr[8];
    float whr[2][5], wlr[2][5];

    // ---- prefetch chunk 0 ----
    {
        const int k0 = 0;
#pragma unroll
        for (int q = 0; q < 8; q++) {
            int i = tid + 256 * q;
            int r = i >> 4, c = i & 15;
            int gr = row0 + r;
            xr[q] = (gr < n) ? X[(size_t)gr * ldx + k0 + c] : 0.f;  // k<16<DNF ok
        }
#pragma unroll
        for (int rr = 0; rr < 2; rr++) {
            int k = k0 + warp * 2 + rr;
            const float* wh = Whi + (size_t)k * WDIM;
            const float* wl = Wlo + (size_t)k * WDIM;
#pragma unroll
            for (int q = 0; q < 5; q++) {
                int cc = lane + 32 * q;
                if (cc < WDIM) { whr[rr][q] = wh[cc]; wlr[rr][q] = wl[cc]; }
            }
        }
    }

    for (int ch = 0; ch < 9; ch++) {
        __syncthreads();   // previous MMA phase done; smem free
        // ---- store prefetched chunk to smem ----
#pragma unroll
        for (int q = 0; q < 8; q++) {
            int i = tid + 256 * q;
            Xs[i >> 4][i & 15] = xr[q];
        }
#pragma unroll
        for (int rr = 0; rr < 2; rr++) {
            int kk = warp * 2 + rr;
#pragma unroll
            for (int q = 0; q < 5; q++) {
                int cc = lane + 32 * q;
                if (cc < WDIM) { Whs[kk][cc] = whr[rr][q]; Wls[kk][cc] = wlr[rr][q]; }
            }
        }
        __syncthreads();

        // ---- issue prefetch loads for chunk ch+1 (overlap with MMAs below) ----
        if (ch < 8) {
            int k0 = (ch + 1) * 16;
#pragma unroll
            for (int q = 0; q < 8; q++) {
                int i = tid + 256 * q;
                int r = i >> 4, c = i & 15;
                int gr = row0 + r, k = k0 + c;
                xr[q] = (gr < n && k < DNF) ? X[(size_t)gr * ldx + k] : 0.f;
            }
#pragma unroll
            for (int rr = 0; rr < 2; rr++) {
                int k = k0 + warp * 2 + rr;
                bool kv = (k < WDIM);
                const float* wh = Whi + (size_t)(kv ? k : 0) * WDIM;
                const float* wl = Wlo + (size_t)(kv ? k : 0) * WDIM;
#pragma unroll
                for (int q = 0; q < 5; q++) {
                    int cc = lane + 32 * q;
                    if (cc < WDIM) {
                        whr[rr][q] = kv ? wh[cc] : 0.f;
                        wlr[rr][q] = kv ? wl[cc] : 0.f;
                    }
                }
            }
        }

        // ---- MMAs for chunk ch: 2 k-steps of 8 ----
#pragma unroll
        for (int ks = 0; ks < 2; ks++) {
            int kb = ks * 8;
            float x00 = Xs[strip + gid][kb + tig];
            float x10 = Xs[strip + gid + 8][kb + tig];
            float x01 = Xs[strip + gid][kb + tig + 4];
            float x11 = Xs[strip + gid + 8][kb + tig + 4];
            uint32_t ah[4], al[4];
            ah[0] = f2tf32(x00); al[0] = f2tf32(x00 - __uint_as_float(ah[0]));
            ah[1] = f2tf32(x10); al[1] = f2tf32(x10 - __uint_as_float(ah[1]));
            ah[2] = f2tf32(x01); al[2] = f2tf32(x01 - __uint_as_float(ah[2]));
            ah[3] = f2tf32(x11); al[3] = f2tf32(x11 - __uint_as_float(ah[3]));

#pragma unroll
            for (int nt = 0; nt < 17; nt++) {
                int nb = nt * 8 + gid;
                uint32_t bh0 = __float_as_uint(Whs[kb + tig][nb]);
                uint32_t bh1 = __float_as_uint(Whs[kb + tig + 4][nb]);
                uint32_t bl0 = __float_as_uint(Wls[kb + tig][nb]);
                uint32_t bl1 = __float_as_uint(Wls[kb + tig + 4][nb]);
                MMA_TF32(acc[nt], ah, bh0, bh1);
                MMA_TF32(acc[nt], ah, bl0, bl1);
                MMA_TF32(acc[nt], al, bh0, bh1);
            }
        }
    }

    // ---- epilogue: D thread layout (gid, 2*tig),(.,+1),(gid+8, 2*tig),(.,+1) ----
    int r0 = row0 + strip + gid;
    int r1 = r0 + 8;
    float d0 = (r0 < n) ? rsqrtf((float)g_deg[r0]) : 0.f;
    float d1 = (r1 < n) ? rsqrtf((float)g_deg[r1]) : 0.f;
#pragma unroll
    for (int nt = 0; nt < 17; nt++) {
        int c0 = nt * 8 + 2 * tig;
        if (r0 < n)
            *(float2*)(g_hp + (size_t)r0 * DPAD + c0) =
                make_float2(acc[nt][0] * d0, acc[nt][1] * d0);
        if (r1 < n)
            *(float2*)(g_hp + (size_t)r1 * DPAD + c0) =
                make_float2(acc[nt][2] * d1, acc[nt][3] * d1);
    }
}

// ---------------- aggregate: g_feat[i] = relu(dinv[i]*(sum_in hp[j] + hp[i]) + b) ----------------
// One warp per node; lane owns float4 at col 4*lane; lanes 0..1 own tail float4s.
__global__ void aggregate_kernel(const float* __restrict__ bias, int n) {
    int node = blockIdx.x * (blockDim.x >> 5) + (threadIdx.x >> 5);
    if (node >= n) return;
    int lane = threadIdx.x & 31;

    const float4* self4 = (const float4*)(g_hp + (size_t)node * DPAD);
    float4 acc = self4[lane];
    float4 acct = make_float4(0.f, 0.f, 0.f, 0.f);
    if (lane < 2) acct = self4[32 + lane];

    int s = g_rowptr[node], e = g_rowptr[node + 1];
    int idx = s;
    for (; idx + 1 < e; idx += 2) {
        int j0 = g_col[idx], j1 = g_col[idx + 1];
        const float4* r0 = (const float4*)(g_hp + (size_t)j0 * DPAD);
        const float4* r1 = (const float4*)(g_hp + (size_t)j1 * DPAD);
        float4 v0 = r0[lane];
        float4 v1 = r1[lane];
        float4 t0, t1;
        if (lane < 2) { t0 = r0[32 + lane]; t1 = r1[32 + lane]; }
        acc.x += v0.x; acc.y += v0.y; acc.z += v0.z; acc.w += v0.w;
        acc.x += v1.x; acc.y += v1.y; acc.z += v1.z; acc.w += v1.w;
        if (lane < 2) {
            acct.x += t0.x; acct.y += t0.y; acct.z += t0.z; acct.w += t0.w;
            acct.x += t1.x; acct.y += t1.y; acct.z += t1.z; acct.w += t1.w;
        }
    }
    if (idx < e) {
        int j0 = g_col[idx];
        const float4* r0 = (const float4*)(g_hp + (size_t)j0 * DPAD);
        float4 v0 = r0[lane];
        acc.x += v0.x; acc.y += v0.y; acc.z += v0.z; acc.w += v0.w;
        if (lane < 2) {
            float4 t0 = r0[32 + lane];
            acct.x += t0.x; acct.y += t0.y; acct.z += t0.z; acct.w += t0.w;
        }
    }

    float di = rsqrtf((float)g_deg[node]);
    float4 o;
    o.x = fmaxf(fmaf(acc.x, di, bias[4 * lane + 0]), 0.f);
    o.y = fmaxf(fmaf(acc.y, di, bias[4 * lane + 1]), 0.f);
    o.z = fmaxf(fmaf(acc.z, di, bias[4 * lane + 2]), 0.f);
    o.w = fmaxf(fmaf(acc.w, di, bias[4 * lane + 3]), 0.f);
    float4* out4 = (float4*)(g_feat + (size_t)node * DPAD);
    out4[lane] = o;
    if (lane == 0) {
        float4 t;
        t.x = fmaxf(fmaf(acct.x, di, bias[128]), 0.f);
        t.y = fmaxf(fmaf(acct.y, di, bias[129]), 0.f);
        t.z = fmaxf(fmaf(acct.z, di, bias[130]), 0.f);
        t.w = fmaxf(fmaf(acct.w, di, bias[131]), 0.f);
        out4[32] = t;
    } else if (lane == 1) {
        float4 t;
        t.x = fmaxf(fmaf(acct.x, di, bias[132]), 0.f);
        t.y = 0.f; t.z = 0.f; t.w = 0.f;   // keep pads zero
        out4[33] = t;
    }
}

// ---------------- global mean pool ----------------
__device__ __forceinline__ int lbound_any(const void* a, int n, int v) {
    int lo = 0, hi = n;
    while (lo < hi) {
        int m = (lo + hi) >> 1;
        long long x = g_is64 ? ((const long long*)a)[m]
                             : (long long)((const int*)a)[m];
        if (x < (long long)v) lo = m + 1; else hi = m;
    }
    return lo;
}

__global__ void pool_kernel(const void* __restrict__ batch,
                            float* __restrict__ out, int n) {
    __shared__ int lo_s, hi_s;
    int g = blockIdx.x;
    if (threadIdx.x == 0) {
        lo_s = lbound_any(batch, n, g);
        hi_s = lbound_any(batch, n, g + 1);
    }
    __syncthreads();
    int lo = lo_s, hi = hi_s;
    int c = threadIdx.x;
    if (c < DNF) {
        float s0 = 0.f, s1 = 0.f, s2 = 0.f, s3 = 0.f;
        int r = lo;
        for (; r + 3 < hi; r += 4) {
            s0 += g_feat[(size_t)(r + 0) * DPAD + c];
            s1 += g_feat[(size_t)(r + 1) * DPAD + c];
            s2 += g_feat[(size_t)(r + 2) * DPAD + c];
            s3 += g_feat[(size_t)(r + 3) * DPAD + c];
        }
        for (; r < hi; r++) s0 += g_feat[(size_t)r * DPAD + c];
        int cnt = hi - lo;
        out[g * DNF + c] = ((s0 + s1) + (s2 + s3)) / (float)(cnt > 0 ? cnt : 1);
    }
}

// ---------------- launch: kernel launches ONLY ----------------
extern "C" void kernel_launch(void* const* d_in, const int* in_sizes, int n_in,
                              void* d_out, int out_size) {
    const float* x     = (const float*)d_in[0];
    const void*  ei    = d_in[1];
    const void*  batch = d_in[2];
    const float* W1    = (const float*)d_in[3];
    const float* b1    = (const float*)d_in[4];
    const float* W2    = (const float*)d_in[5];
    const float* b2    = (const float*)d_in[6];
    float* out = (float*)d_out;

    int n = in_sizes[0] / DNF;   // 50000
    int e = in_sizes[1] / 2;     // 800000

    int tb = 256;
    int gn = (n + tb - 1) / tb;  // 196
    int ge = (e + tb - 1) / tb;

    int gemm_blocks = (n + 127) / 128;   // 391
    int agg_blocks  = (n + 7) / 8;

    prologue_kernel<<<gn, tb>>>((const int*)ei, n);       // 1: deg=1 + dtype detect
    count_deg_kernel<<<ge, tb>>>(ei, e);                  // 2
    wconv_kernel<<<dim3(WDIM, 2), 160>>>(W1, W2);         // 3: tf32 hi/lo split
    gemm_mma_kernel<<<gemm_blocks, 256>>>(x, 0, 1, n);    // 4 <- profiled slot
    partial_kernel<<<gn, tb>>>(n);                        // 5
    finalize_kernel<<<gn, tb>>>(n, e);                    // 6: rowptr+pos
    fill_kernel<<<ge, tb>>>(ei, e);                       // 7
    aggregate_kernel<<<agg_blocks, 256>>>(b1, n);         // 8
    gemm_mma_kernel<<<gemm_blocks, 256>>>(x, 1, 0, n);    // 9
    aggregate_kernel<<<agg_blocks, 256>>>(b2, n);         // 10
    pool_kernel<<<NGRAPH, 160>>>(batch, out, n);          // 11
}

// round 13
// speedup vs baseline: 1.8149x; 1.0349x over previous
#include <cuda_runtime.h>
#include <cstdint>

#define DNF  133
#define DPAD 136   // padded feature stride: 544 B rows, float4-aligned
#define MAXN 50000
#define MAXE 800000
#define NGRAPH 256
#define WDIM 136   // padded W dim for mma (17 n-tiles of 8, 17 k-steps of 8)
#define LDW  140   // smem row stride (float2) -> even bank spread {0,24,16,8}

// ---------------- static device scratch (zero-initialized at load) ----------------
__device__ float g_hp[MAXN * DPAD];    // (X@W) * dinv[row]; cols 133..135 stay 0
__device__ float g_feat[MAXN * DPAD];  // layer outputs;     cols 133..135 stay 0
__device__ int   g_deg[MAXN];
__device__ int   g_rowptr[MAXN + 1];
__device__ int   g_pos[MAXN];
__device__ int   g_col[MAXE];
__device__ int   g_bsum[256];
__device__ int   g_is64;
// W split into tf32 (hi,lo) float2 pairs, [k][n] layout, zero-padded
__device__ float2 g_Whl[2][WDIM * WDIM];

// ---------------- tf32 helpers ----------------
__device__ __forceinline__ uint32_t f2tf32(float f) {
    uint32_t u;
    asm("cvt.rna.tf32.f32 %0, %1;" : "=r"(u) : "f"(f));
    return u;
}
// D(16x8,f32) += A(16x8,tf32,row) * B(8x8,tf32,col)
#define MMA_TF32(d, a, b0, b1) \
    asm("mma.sync.aligned.m16n8k8.row.col.f32.tf32.tf32.f32 " \
        "{%0,%1,%2,%3}, {%4,%5,%6,%7}, {%8,%9}, {%0,%1,%2,%3};" \
        : "+f"((d)[0]), "+f"((d)[1]), "+f"((d)[2]), "+f"((d)[3]) \
        : "r"((a)[0]), "r"((a)[1]), "r"((a)[2]), "r"((a)[3]), "r"(b0), "r"(b1))

// ---------------- prologue: deg=1 (self loop) + dtype detect ----------------
__global__ void prologue_kernel(const int* __restrict__ w, int n) {
    int i = blockIdx.x * blockDim.x + threadIdx.x;
    if (i < n) g_deg[i] = 1;
    if (blockIdx.x == 0 && threadIdx.x < 32) {
        int lane = threadIdx.x;
        int bad = 0;
#pragma unroll
        for (int it = 0; it < 32; it++)
            bad |= w[2 * (lane + 32 * it) + 1];
        unsigned any = __ballot_sync(0xffffffffu, bad != 0);
        if (lane == 0) g_is64 = (any == 0u) ? 1 : 0;
    }
}

__device__ __forceinline__ int load_idx(const void* p, long long i) {
    return g_is64 ? (int)((const long long*)p)[i] : ((const int*)p)[i];
}

__global__ void count_deg_kernel(const void* __restrict__ ei, int e) {
    int i = blockIdx.x * blockDim.x + threadIdx.x;
    if (i < e) atomicAdd(&g_deg[load_idx(ei, (long long)e + i)], 1);
}

// ---------------- W split: g_Whl[w][k][n] = (tf32_hi, tf32_lo) of W[k][n] ----------------
__global__ void wconv_kernel(const float* __restrict__ W1,
                             const float* __restrict__ W2) {
    int k = blockIdx.x, w = blockIdx.y, nn = threadIdx.x;
    if (nn >= WDIM) return;
    const float* W = w ? W2 : W1;
    float v = (k < DNF && nn < DNF) ? W[k * DNF + nn] : 0.f;
    uint32_t uh = f2tf32(v);
    float vh = __uint_as_float(uh);
    uint32_t ul = f2tf32(v - vh);
    g_Whl[w][k * WDIM + nn] = make_float2(vh, __uint_as_float(ul));
}

// ---------------- 2-level parallel exclusive scan of (deg-1) ----------------
__global__ void partial_kernel(int n) {
    __shared__ int wsum[8];
    int i = blockIdx.x * blockDim.x + threadIdx.x;
    int d = (i < n) ? g_deg[i] - 1 : 0;
    int lane = threadIdx.x & 31, wid = threadIdx.x >> 5;
#pragma unroll
    for (int o = 16; o > 0; o >>= 1) d += __shfl_down_sync(0xffffffffu, d, o);
    if (lane == 0) wsum[wid] = d;
    __syncthreads();
    if (wid == 0) {
        int s = (lane < 8) ? wsum[lane] : 0;
#pragma unroll
        for (int o = 4; o > 0; o >>= 1) s += __shfl_down_sync(0xffffffffu, s, o);
        if (lane == 0) g_bsum[blockIdx.x] = s;
    }
}

__global__ void finalize_kernel(int n, int e) {
    __shared__ int wsum[8];
    __shared__ int off_s;
    int tid = threadIdx.x, bid = blockIdx.x;
    int lane = tid & 31, wid = tid >> 5;
    {
        int v = (tid < bid) ? g_bsum[tid] : 0;
#pragma unroll
        for (int o = 16; o > 0; o >>= 1) v += __shfl_down_sync(0xffffffffu, v, o);
        if (lane == 0) wsum[wid] = v;
        __syncthreads();
        if (wid == 0) {
            int s = (lane < 8) ? wsum[lane] : 0;
#pragma unroll
            for (int o = 4; o > 0; o >>= 1) s += __shfl_down_sync(0xffffffffu, s, o);
            if (lane == 0) off_s = s;
        }
        __syncthreads();
    }
    int offset = off_s;
    __syncthreads();

    int i = bid * blockDim.x + tid;
    int deg = (i < n) ? g_deg[i] : 1;
    int d = (i < n) ? deg - 1 : 0;
    int v = d;
#pragma unroll
    for (int o = 1; o < 32; o <<= 1) {
        int t = __shfl_up_sync(0xffffffffu, v, o);
        if (lane >= o) v += t;
    }
    if (lane == 31) wsum[wid] = v;
    __syncthreads();
    if (wid == 0) {
        int s = (lane < 8) ? wsum[lane] : 0;
#pragma unroll
        for (int o = 1; o < 8; o <<= 1) {
            int t = __shfl_up_sync(0xffffffffu, s, o);
            if (lane >= o) s += t;
        }
        if (lane < 8) wsum[lane] = s;
    }
    __syncthreads();
    int excl = v - d + ((wid > 0) ? wsum[wid - 1] : 0);
    if (i < n) {
        int rp = offset + excl;
        g_rowptr[i] = rp;
        g_pos[i] = rp;
    }
    if (i == 0) g_rowptr[n] = e;
}

__global__ void fill_kernel(const void* __restrict__ ei, int e) {
    int i = blockIdx.x * blockDim.x + threadIdx.x;
    if (i < e) {
        int sidx = load_idx(ei, i);
        int d    = load_idx(ei, (long long)e + i);
        g_col[atomicAdd(&g_pos[d], 1)] = sidx;
    }
}

// ---------------- tensor-core GEMM (tf32 split, double-buffered W, direct-A) ----------------
// Block: 256 threads = 8 warps, 128 rows x 136 cols. Warp = 16-row strip.
// A-fragments are thread-exclusive: prefetched straight from gmem (L2) into the
// 8 regs the MMA consumes -- no smem staging. W staged in double-buffered smem
// as (hi,lo) float2 -> 2 LDS.64 per n-tile. ONE barrier per chunk.
__global__ void __launch_bounds__(256)
gemm_mma_kernel(const float* __restrict__ Xext, int widx, int use_ext, int n) {
    __shared__ float2 Wbuf[2][16 * LDW];   // 2 x 17920 B

    const float* X = use_ext ? Xext : (const float*)g_feat;
    int ldx = use_ext ? DNF : DPAD;
    const float2* Whl = g_Whl[widx];

    int tid = threadIdx.x;
    int lane = tid & 31, warp = tid >> 5;
    int row0 = blockIdx.x * 128;
    int strip = warp * 16;
    int gid = lane >> 2;    // 0..7
    int tig = lane & 3;     // 0..3

    int ra = row0 + strip + gid;
    int rb = ra + 8;
    bool va = (ra < n), vb = (rb < n);
    const float* Xa = X + (size_t)(va ? ra : 0) * ldx;
    const float* Xb = X + (size_t)(vb ? rb : 0) * ldx;

    float acc[17][4];
#pragma unroll
    for (int t = 0; t < 17; t++)
#pragma unroll
        for (int j = 0; j < 4; j++) acc[t][j] = 0.f;

    float  xr[2][8];        // [parity][ks*4 + {a0,b0,a1,b1}]
    float2 wld[2][5];       // W prefetch regs: 2 k-rows x 5 col-groups

    // ---- prologue: chunk 0 ----
#pragma unroll
    for (int ks = 0; ks < 2; ks++) {
        int c0 = 8 * ks + tig, c1 = c0 + 4;
        xr[0][4 * ks + 0] = va ? Xa[c0] : 0.f;    // k < 16 < DNF
        xr[0][4 * ks + 1] = vb ? Xb[c0] : 0.f;
        xr[0][4 * ks + 2] = va ? Xa[c1] : 0.f;
        xr[0][4 * ks + 3] = vb ? Xb[c1] : 0.f;
    }
#pragma unroll
    for (int rr = 0; rr < 2; rr++) {
        int k = warp * 2 + rr;
        const float2* wp = Whl + (size_t)k * WDIM;
#pragma unroll
        for (int q = 0; q < 5; q++) {
            int cc = lane + 32 * q;
            wld[rr][q] = (cc < WDIM) ? wp[cc] : make_float2(0.f, 0.f);
        }
    }
#pragma unroll
    for (int rr = 0; rr < 2; rr++)
#pragma unroll
        for (int q = 0; q < 5; q++) {
            int cc = lane + 32 * q;
            if (cc < WDIM) Wbuf[0][(warp * 2 + rr) * LDW + cc] = wld[rr][q];
        }
    __syncthreads();

#pragma unroll
    for (int ch = 0; ch < 9; ch++) {
        const int cur = ch & 1, nxt = cur ^ 1;

        // ---- issue gmem prefetch for chunk ch+1 (drains behind MMAs) ----
        if (ch < 8) {
            int k0 = (ch + 1) * 16;
#pragma unroll
            for (int ks = 0; ks < 2; ks++) {
                int c0 = k0 + 8 * ks + tig, c1 = c0 + 4;
                xr[nxt][4 * ks + 0] = (va && c0 < DNF) ? Xa[c0] : 0.f;
                xr[nxt][4 * ks + 1] = (vb && c0 < DNF) ? Xb[c0] : 0.f;
                xr[nxt][4 * ks + 2] = (va && c1 < DNF) ? Xa[c1] : 0.f;
                xr[nxt][4 * ks + 3] = (vb && c1 < DNF) ? Xb[c1] : 0.f;
            }
#pragma unroll
            for (int rr = 0; rr < 2; rr++) {
                int k = k0 + warp * 2 + rr;
                bool kv = (k < WDIM);
                const float2* wp = Whl + (size_t)(kv ? k : 0) * WDIM;
#pragma unroll
                for (int q = 0; q < 5; q++) {
                    int cc = lane + 32 * q;
                    wld[rr][q] = (kv && cc < WDIM) ? wp[cc] : make_float2(0.f, 0.f);
                }
            }
        }

        // ---- MMAs for chunk ch ----
#pragma unroll
        for (int ks = 0; ks < 2; ks++) {
            float x00 = xr[cur][4 * ks + 0];
            float x10 = xr[cur][4 * ks + 1];
            float x01 = xr[cur][4 * ks + 2];
            float x11 = xr[cur][4 * ks + 3];
            uint32_t ah[4], al[4];
            ah[0] = f2tf32(x00); al[0] = f2tf32(x00 - __uint_as_float(ah[0]));
            ah[1] = f2tf32(x10); al[1] = f2tf32(x10 - __uint_as_float(ah[1]));
            ah[2] = f2tf32(x01); al[2] = f2tf32(x01 - __uint_as_float(ah[2]));
            ah[3] = f2tf32(x11); al[3] = f2tf32(x11 - __uint_as_float(ah[3]));

            int rb0 = (8 * ks + tig) * LDW;
            int rb1 = (8 * ks + tig + 4) * LDW;
#pragma unroll
            for (int nt = 0; nt < 17; nt++) {
                int nb = nt * 8 + gid;
                float2 b0 = Wbuf[cur][rb0 + nb];
                float2 b1 = Wbuf[cur][rb1 + nb];
                MMA_TF32(acc[nt], ah, __float_as_uint(b0.x), __float_as_uint(b1.x));
                MMA_TF32(acc[nt], ah, __float_as_uint(b0.y), __float_as_uint(b1.y));
                MMA_TF32(acc[nt], al, __float_as_uint(b0.x), __float_as_uint(b1.x));
            }
        }

        // ---- store W(ch+1) into the other buffer; single barrier ----
        if (ch < 8) {
#pragma unroll
            for (int rr = 0; rr < 2; rr++)
#pragma unroll
                for (int q = 0; q < 5; q++) {
                    int cc = lane + 32 * q;
                    if (cc < WDIM) Wbuf[nxt][(warp * 2 + rr) * LDW + cc] = wld[rr][q];
                }
            __syncthreads();
        }
    }

    // ---- epilogue: D thread layout (gid, 2*tig),(.,+1),(gid+8, 2*tig),(.,+1) ----
    float d0 = va ? rsqrtf((float)g_deg[ra]) : 0.f;
    float d1 = vb ? rsqrtf((float)g_deg[rb]) : 0.f;
#pragma unroll
    for (int nt = 0; nt < 17; nt++) {
        int c0 = nt * 8 + 2 * tig;
        if (va)
            *(float2*)(g_hp + (size_t)ra * DPAD + c0) =
                make_float2(acc[nt][0] * d0, acc[nt][1] * d0);
        if (vb)
            *(float2*)(g_hp + (size_t)rb * DPAD + c0) =
                make_float2(acc[nt][2] * d1, acc[nt][3] * d1);
    }
}

// ---------------- aggregate: g_feat[i] = relu(dinv[i]*(sum_in hp[j] + hp[i]) + b) ----------------
__global__ void aggregate_kernel(const float* __restrict__ bias, int n) {
    int node = blockIdx.x * (blockDim.x >> 5) + (threadIdx.x >> 5);
    if (node >= n) return;
    int lane = threadIdx.x & 31;

    const float4* self4 = (const float4*)(g_hp + (size_t)node * DPAD);
    float4 acc = self4[lane];
    float4 acct = make_float4(0.f, 0.f, 0.f, 0.f);
    if (lane < 2) acct = self4[32 + lane];

    int s = g_rowptr[node], e = g_rowptr[node + 1];
    int idx = s;
    for (; idx + 1 < e; idx += 2) {
        int j0 = g_col[idx], j1 = g_col[idx + 1];
        const float4* r0 = (const float4*)(g_hp + (size_t)j0 * DPAD);
        const float4* r1 = (const float4*)(g_hp + (size_t)j1 * DPAD);
        float4 v0 = r0[lane];
        float4 v1 = r1[lane];
        float4 t0, t1;
        if (lane < 2) { t0 = r0[32 + lane]; t1 = r1[32 + lane]; }
        acc.x += v0.x; acc.y += v0.y; acc.z += v0.z; acc.w += v0.w;
        acc.x += v1.x; acc.y += v1.y; acc.z += v1.z; acc.w += v1.w;
        if (lane < 2) {
            acct.x += t0.x; acct.y += t0.y; acct.z += t0.z; acct.w += t0.w;
            acct.x += t1.x; acct.y += t1.y; acct.z += t1.z; acct.w += t1.w;
        }
    }
    if (idx < e) {
        int j0 = g_col[idx];
        const float4* r0 = (const float4*)(g_hp + (size_t)j0 * DPAD);
        float4 v0 = r0[lane];
        acc.x += v0.x; acc.y += v0.y; acc.z += v0.z; acc.w += v0.w;
        if (lane < 2) {
            float4 t0 = r0[32 + lane];
            acct.x += t0.x; acct.y += t0.y; acct.z += t0.z; acct.w += t0.w;
        }
    }

    float di = rsqrtf((float)g_deg[node]);
    float4 o;
    o.x = fmaxf(fmaf(acc.x, di, bias[4 * lane + 0]), 0.f);
    o.y = fmaxf(fmaf(acc.y, di, bias[4 * lane + 1]), 0.f);
    o.z = fmaxf(fmaf(acc.z, di, bias[4 * lane + 2]), 0.f);
    o.w = fmaxf(fmaf(acc.w, di, bias[4 * lane + 3]), 0.f);
    float4* out4 = (float4*)(g_feat + (size_t)node * DPAD);
    out4[lane] = o;
    if (lane == 0) {
        float4 t;
        t.x = fmaxf(fmaf(acct.x, di, bias[128]), 0.f);
        t.y = fmaxf(fmaf(acct.y, di, bias[129]), 0.f);
        t.z = fmaxf(fmaf(acct.z, di, bias[130]), 0.f);
        t.w = fmaxf(fmaf(acct.w, di, bias[131]), 0.f);
        out4[32] = t;
    } else if (lane == 1) {
        float4 t;
        t.x = fmaxf(fmaf(acct.x, di, bias[132]), 0.f);
        t.y = 0.f; t.z = 0.f; t.w = 0.f;   // keep pads zero
        out4[33] = t;
    }
}

// ---------------- global mean pool ----------------
__device__ __forceinline__ int lbound_any(const void* a, int n, int v) {
    int lo = 0, hi = n;
    while (lo < hi) {
        int m = (lo + hi) >> 1;
        long long x = g_is64 ? ((const long long*)a)[m]
                             : (long long)((const int*)a)[m];
        if (x < (long long)v) lo = m + 1; else hi = m;
    }
    return lo;
}

__global__ void pool_kernel(const void* __restrict__ batch,
                            float* __restrict__ out, int n) {
    __shared__ int lo_s, hi_s;
    int g = blockIdx.x;
    if (threadIdx.x == 0) {
        lo_s = lbound_any(batch, n, g);
        hi_s = lbound_any(batch, n, g + 1);
    }
    __syncthreads();
    int lo = lo_s, hi = hi_s;
    int c = threadIdx.x;
    if (c < DNF) {
        float s0 = 0.f, s1 = 0.f, s2 = 0.f, s3 = 0.f;
        int r = lo;
        for (; r + 3 < hi; r += 4) {
            s0 += g_feat[(size_t)(r + 0) * DPAD + c];
            s1 += g_feat[(size_t)(r + 1) * DPAD + c];
            s2 += g_feat[(size_t)(r + 2) * DPAD + c];
            s3 += g_feat[(size_t)(r + 3) * DPAD + c];
        }
        for (; r < hi; r++) s0 += g_feat[(size_t)r * DPAD + c];
        int cnt = hi - lo;
        out[g * DNF + c] = ((s0 + s1) + (s2 + s3)) / (float)(cnt > 0 ? cnt : 1);
    }
}

// ---------------- launch: kernel launches ONLY ----------------
extern "C" void kernel_launch(void* const* d_in, const int* in_sizes, int n_in,
                              void* d_out, int out_size) {
    const float* x     = (const float*)d_in[0];
    const void*  ei    = d_in[1];
    const void*  batch = d_in[2];
    const float* W1    = (const float*)d_in[3];
    const float* b1    = (const float*)d_in[4];
    const float* W2    = (const float*)d_in[5];
    const float* b2    = (const float*)d_in[6];
    float* out = (float*)d_out;

    int n = in_sizes[0] / DNF;   // 50000
    int e = in_sizes[1] / 2;     // 800000

    int tb = 256;
    int gn = (n + tb - 1) / tb;  // 196
    int ge = (e + tb - 1) / tb;

    int gemm_blocks = (n + 127) / 128;   // 391
    int agg_blocks  = (n + 7) / 8;

    prologue_kernel<<<gn, tb>>>((const int*)ei, n);       // 1: deg=1 + dtype detect
    count_deg_kernel<<<ge, tb>>>(ei, e);                  // 2
    wconv_kernel<<<dim3(WDIM, 2), 160>>>(W1, W2);         // 3: tf32 (hi,lo) pack
    gemm_mma_kernel<<<gemm_blocks, 256>>>(x, 0, 1, n);    // 4 <- profiled slot
    partial_kernel<<<gn, tb>>>(n);                        // 5
    finalize_kernel<<<gn, tb>>>(n, e);                    // 6: rowptr+pos
    fill_kernel<<<ge, tb>>>(ei, e);                       // 7
    aggregate_kernel<<<agg_blocks, 256>>>(b1, n);         // 8
    gemm_mma_kernel<<<gemm_blocks, 256>>>(x, 1, 0, n);    // 9
    aggregate_kernel<<<agg_blocks, 256>>>(b2, n);         // 10
    pool_kernel<<<NGRAPH, 160>>>(batch, out, n);          // 11
}